// round 17
// baseline (speedup 1.0000x reference)
#include <cuda_runtime.h>

// Sobel |gx|+|gy|+eps over (32,1,1024,1024) f32, SAME zero padding.
// SINGLE exact wave: 740 blocks = 148 SMs x 5 resident blocks, each block
// covers a 44/45-row strip of the flattened 32768-row space (strips may
// cross image boundaries; vertical pad applied per-row via FMA masks).
// Pipeline: 3-row rolling register window, raw rows prefetched 2 iterations
// ahead, shuffle halo, .cs streaming stores. Rolled loop (unroll 4).

#define IMG_W 1024
#define G_ROWS 32768        // 32 images * 1024 rows, flattened
#define NBLK  740           // one exact wave at 5 blocks/SM on 148 SMs
#define B45   208           // first B45 blocks do 45 rows, rest 44

struct RawRow {
    float4 c;
    float  e;   // lane 0: left halo; lane 31: right halo; others unused
};

__device__ __forceinline__ RawRow load_raw(const float* __restrict__ base,
                                           bool in, int c4, int lane) {
    RawRow o;
    o.c = make_float4(0.f, 0.f, 0.f, 0.f);
    o.e = 0.f;
    if (in) {
        o.c = *reinterpret_cast<const float4*>(base);
        if (lane == 0) {
            if (c4 > 0) o.e = __ldg(base - 1);
        } else if (lane == 31) {
            if (c4 < 255) o.e = __ldg(base + 4);
        }
    }
    return o;
}

__device__ __forceinline__ void expand(const RawRow& rr, int lane, float v[6]) {
    float left  = __shfl_up_sync(0xFFFFFFFFu, rr.c.w, 1);
    float right = __shfl_down_sync(0xFFFFFFFFu, rr.c.x, 1);
    if (lane == 0)  left  = rr.e;
    if (lane == 31) right = rr.e;
    v[0] = left;
    v[1] = rr.c.x; v[2] = rr.c.y; v[3] = rr.c.z; v[4] = rr.c.w;
    v[5] = right;
}

__global__ void __launch_bounds__(256, 5)
sobel_grad_kernel(const float* __restrict__ x, float* __restrict__ out) {
    int c4   = threadIdx.x;            // float4 column (0..255)
    int lane = c4 & 31;
    int b    = blockIdx.x;

    int row0 = 44 * b + min(b, B45);   // flattened start row
    int h    = (b < B45) ? 45 : 44;    // rows this block

    const float* ibase = x   + (size_t)c4 * 4;
    float*       obase = out + (size_t)c4 * 4 + (size_t)row0 * IMG_W;

    float top[6], mid[6], bot[6];
    RawRow praw;

    // Prologue: flattened rows row0-1 .. row0+1 expanded, row0+2 raw.
    {
        const float* p = ibase + (size_t)(row0 - 1) * IMG_W;
        RawRow r0 = load_raw(p,             row0 - 1 >= 0,       c4, lane);
        RawRow r1 = load_raw(p + IMG_W,     true,                c4, lane);
        RawRow r2 = load_raw(p + 2 * IMG_W, row0 + 1 < G_ROWS,   c4, lane);
        praw      = load_raw(p + 3 * IMG_W, row0 + 2 < G_ROWS,   c4, lane);
        expand(r0, lane, top);
        expand(r1, lane, mid);
        expand(r2, lane, bot);
    }

    const float* pf = ibase + (size_t)(row0 + 3) * IMG_W;

    #pragma unroll 4
    for (int i = 0; i < h; i++) {
        // Raw prefetch flattened row row0+i+3 (consumed 2 iters later).
        RawRow nraw;
        if (i < h - 2)
            nraw = load_raw(pf, row0 + i + 3 < G_ROWS, c4, lane);
        pf += IMG_W;

        // Vertical zero-pad masks at image boundaries, folded into FMAs.
        int rmod = (row0 + i) & 1023;
        float mt = (rmod != 0)    ? 1.0f : 0.0f;
        float mb = (rmod != 1023) ? 1.0f : 0.0f;

        float o[4];
        #pragma unroll
        for (int j = 0; j < 4; j++) {
            float dt = top[j + 2] - top[j];
            float dm = mid[j + 2] - mid[j];
            float db = bot[j + 2] - bot[j];
            float gx = fmaf(mt, dt, fmaf(mb, db, 2.0f * dm));
            float st = top[j] + 2.0f * top[j + 1] + top[j + 2];
            float sb = bot[j] + 2.0f * bot[j + 1] + bot[j + 2];
            float gy = fmaf(mb, sb, -(mt * st));
            o[j] = fabsf(gx) + fabsf(gy) + 1e-5f;
        }
        __stcs(reinterpret_cast<float4*>(obase), make_float4(o[0], o[1], o[2], o[3]));
        obase += IMG_W;

        #pragma unroll
        for (int k = 0; k < 6; k++) { top[k] = mid[k]; mid[k] = bot[k]; }
        expand(praw, lane, bot);
        praw = nraw;
    }
}

extern "C" void kernel_launch(void* const* d_in, const int* in_sizes, int n_in,
                              void* d_out, int out_size) {
    const float* x = (const float*)d_in[0];
    float* out = (float*)d_out;

    sobel_grad_kernel<<<NBLK, 256>>>(x, out);
}